// round 4
// baseline (speedup 1.0000x reference)
#include <cuda_runtime.h>
#include <math.h>

#define BB 32
#define MM 8192
#define II 256
#define BLOCKS_PER_B 32
#define WARPS_PER_BLOCK 8
#define PPB (BLOCKS_PER_B * WARPS_PER_BLOCK)   /* 256 merged partials per batch */
#define HALVES_PER_B (PPB * 2)                 /* 512 half-warps per batch */
#define ROWS_PER_HALF (MM / HALVES_PER_B)      /* 16 rows per half-warp */

/* Static device scratch (no allocations allowed). */
__device__ float g_pk[BB * II];                /* projected key, 32 KB   */
__device__ float g_acc[BB * PPB * II];         /* partial accums, 8 MB   */
__device__ float g_ms[BB * PPB];               /* partial running max    */
__device__ float g_ls[BB * PPB];               /* partial running sum    */
__device__ float g_bmax[BB];                   /* final per-batch max    */
__device__ float g_bsum[BB];                   /* final per-batch sum    */

/* ------------------------------------------------------------------ */
/* 1) projected_key = tanh(key @ W^T + b)   grid=B, block=256          */
/* ------------------------------------------------------------------ */
__global__ void proj_kernel(const float* __restrict__ key,
                            const float* __restrict__ W,
                            const float* __restrict__ bias)
{
    __shared__ float sk[II];
    const int b = blockIdx.x;
    const int i = threadIdx.x;
    sk[i] = key[b * II + i];
    __syncthreads();

    const float* wr = W + (size_t)i * II;   /* torch Linear weight: [out, in] */
    float acc = bias[i];
#pragma unroll 8
    for (int k = 0; k < II; k++)
        acc = fmaf(sk[k], __ldg(&wr[k]), acc);

    g_pk[b * II + i] = tanhf(acc);
}

/* ------------------------------------------------------------------ */
/* 2) Single pass: similarity + online-softmax partials.               */
/*    Half-warp per row: 16 lanes x 16 cols/lane. 4-level shuffle.     */
/*    Explicit next-row prefetch overlaps DRAM latency with reduce.    */
/* ------------------------------------------------------------------ */
__global__ void __launch_bounds__(256, 2)
main_kernel(const float* __restrict__ memory,
            const float* __restrict__ beta,
            float* __restrict__ sim_out)
{
    const int b    = blockIdx.x >> 5;          /* / BLOCKS_PER_B      */
    const int blk  = blockIdx.x & 31;
    const int warp = threadIdx.x >> 5;
    const int lane = threadIdx.x & 31;
    const int lh   = lane & 15;                /* lane within half    */
    const int half = lane >> 4;
    const int p    = blk * WARPS_PER_BLOCK + warp;  /* merged 0..255  */
    const int p2   = p * 2 + half;                  /* half   0..511  */

    /* pk columns for this lane: float4 indices lh, 16+lh, 32+lh, 48+lh */
    const float4* pkv = (const float4*)(g_pk + b * II);
    const float4 k0 = pkv[lh], k1 = pkv[16 + lh];
    const float4 k2 = pkv[32 + lh], k3 = pkv[48 + lh];
    const float  bet = beta[b];

    const float4* rowp = (const float4*)(memory +
                        ((size_t)b * MM + (size_t)p2 * ROWS_PER_HALF) * II);
    float* srow = sim_out + (size_t)b * MM + (size_t)p2 * ROWS_PER_HALF;

    float  ms = -INFINITY, ls = 0.0f;
    float4 a0 = make_float4(0.f,0.f,0.f,0.f), a1 = a0, a2 = a0, a3 = a0;

    /* preload row 0 */
    float4 x0 = rowp[lh], x1 = rowp[16 + lh];
    float4 x2 = rowp[32 + lh], x3 = rowp[48 + lh];

#pragma unroll 2
    for (int r = 0; r < ROWS_PER_HALF; r++) {
        /* prefetch next row before touching current row's chain */
        const float4* nxt = rowp + (II / 4);
        float4 y0, y1, y2, y3;
        if (r < ROWS_PER_HALF - 1) {
            y0 = nxt[lh];      y1 = nxt[16 + lh];
            y2 = nxt[32 + lh]; y3 = nxt[48 + lh];
        }

        /* per-lane squared-diff over 16 columns, 4 independent chains */
        float t, da, db, dc, dd;
        t = k0.x - x0.x; da  = t * t;  t = k1.x - x1.x; db  = t * t;
        t = k2.x - x2.x; dc  = t * t;  t = k3.x - x3.x; dd  = t * t;
        t = k0.y - x0.y; da += t * t;  t = k1.y - x1.y; db += t * t;
        t = k2.y - x2.y; dc += t * t;  t = k3.y - x3.y; dd += t * t;
        t = k0.z - x0.z; da += t * t;  t = k1.z - x1.z; db += t * t;
        t = k2.z - x2.z; dc += t * t;  t = k3.z - x3.z; dd += t * t;
        t = k0.w - x0.w; da += t * t;  t = k1.w - x1.w; db += t * t;
        t = k2.w - x2.w; dc += t * t;  t = k3.w - x3.w; dd += t * t;
        float d = (da + db) + (dc + dd);

        /* 4-level butterfly within each 16-lane half */
        d += __shfl_xor_sync(0xffffffffu, d, 8);
        d += __shfl_xor_sync(0xffffffffu, d, 4);
        d += __shfl_xor_sync(0xffffffffu, d, 2);
        d += __shfl_xor_sync(0xffffffffu, d, 1);

        if (lh == 0) srow[r] = -d;          /* similarity output */

        const float s = -bet * d;
        if (s > ms) {                        /* rare: rescale state */
            const float c = __expf(ms - s);  /* first iter: exp(-inf)=0 */
            ls = ls * c + 1.0f;
            a0.x = fmaf(a0.x, c, x0.x); a0.y = fmaf(a0.y, c, x0.y);
            a0.z = fmaf(a0.z, c, x0.z); a0.w = fmaf(a0.w, c, x0.w);
            a1.x = fmaf(a1.x, c, x1.x); a1.y = fmaf(a1.y, c, x1.y);
            a1.z = fmaf(a1.z, c, x1.z); a1.w = fmaf(a1.w, c, x1.w);
            a2.x = fmaf(a2.x, c, x2.x); a2.y = fmaf(a2.y, c, x2.y);
            a2.z = fmaf(a2.z, c, x2.z); a2.w = fmaf(a2.w, c, x2.w);
            a3.x = fmaf(a3.x, c, x3.x); a3.y = fmaf(a3.y, c, x3.y);
            a3.z = fmaf(a3.z, c, x3.z); a3.w = fmaf(a3.w, c, x3.w);
            ms = s;
        } else {
            const float w = __expf(s - ms);
            ls += w;
            a0.x = fmaf(w, x0.x, a0.x); a0.y = fmaf(w, x0.y, a0.y);
            a0.z = fmaf(w, x0.z, a0.z); a0.w = fmaf(w, x0.w, a0.w);
            a1.x = fmaf(w, x1.x, a1.x); a1.y = fmaf(w, x1.y, a1.y);
            a1.z = fmaf(w, x1.z, a1.z); a1.w = fmaf(w, x1.w, a1.w);
            a2.x = fmaf(w, x2.x, a2.x); a2.y = fmaf(w, x2.y, a2.y);
            a2.z = fmaf(w, x2.z, a2.z); a2.w = fmaf(w, x2.w, a2.w);
            a3.x = fmaf(w, x3.x, a3.x); a3.y = fmaf(w, x3.y, a3.y);
            a3.z = fmaf(w, x3.z, a3.z); a3.w = fmaf(w, x3.w, a3.w);
        }

        rowp = nxt;
        x0 = y0; x1 = y1; x2 = y2; x3 = y3;
    }

    /* ---- merge the two half-warp states (shfl_xor 16) ---- */
    const unsigned FU = 0xffffffffu;
    const float mo = __shfl_xor_sync(FU, ms, 16);
    const float lo = __shfl_xor_sync(FU, ls, 16);
    const float mM = fmaxf(ms, mo);
    const float cS = __expf(ms - mM);
    const float cO = __expf(mo - mM);
    const float lsm = fmaf(ls, cS, lo * cO);

#define MRG(f) f = fmaf(f, cS, __shfl_xor_sync(FU, f, 16) * cO)
    MRG(a0.x); MRG(a0.y); MRG(a0.z); MRG(a0.w);
    MRG(a1.x); MRG(a1.y); MRG(a1.z); MRG(a1.w);
    MRG(a2.x); MRG(a2.y); MRG(a2.z); MRG(a2.w);
    MRG(a3.x); MRG(a3.y); MRG(a3.z); MRG(a3.w);
#undef MRG

    float4* accp = (float4*)(g_acc + (size_t)(b * PPB + p) * II);
    if (half == 0) {
        accp[lh]      = a0;
        accp[16 + lh] = a1;
        accp[32 + lh] = a2;
        accp[48 + lh] = a3;
    }
    if (lane == 0) {
        g_ms[b * PPB + p] = mM;
        g_ls[b * PPB + p] = lsm;
    }
}

/* ------------------------------------------------------------------ */
/* 3) Merge 256 partials per batch -> read_vector + (bmax, bsum).      */
/*    grid = B, block = 256 (thread t -> column t)                     */
/* ------------------------------------------------------------------ */
__global__ void combine_kernel(float* __restrict__ read_out)
{
    __shared__ float sscale[PPB];
    __shared__ float sred[32];
    __shared__ float sbroad[2];

    const int b    = blockIdx.x;
    const int t    = threadIdx.x;
    const int lane = t & 31;
    const int wrp  = t >> 5;

    float m = g_ms[b * PPB + t];
    float mv = m;
#pragma unroll
    for (int sh = 16; sh >= 1; sh >>= 1)
        mv = fmaxf(mv, __shfl_xor_sync(0xffffffffu, mv, sh));
    if (lane == 0) sred[wrp] = mv;
    __syncthreads();
    if (t == 0) {
        float mm = sred[0];
        for (int q = 1; q < 8; q++) mm = fmaxf(mm, sred[q]);
        sbroad[0] = mm;
    }
    __syncthreads();
    const float Mb = sbroad[0];

    const float sc = __expf(m - Mb);
    sscale[t] = sc;

    float sv = g_ls[b * PPB + t] * sc;
#pragma unroll
    for (int sh = 16; sh >= 1; sh >>= 1)
        sv += __shfl_xor_sync(0xffffffffu, sv, sh);
    if (lane == 0) sred[wrp] = sv;
    __syncthreads();
    if (t == 0) {
        float su = 0.0f;
        for (int q = 0; q < 8; q++) su += sred[q];
        g_bmax[b] = Mb;
        g_bsum[b] = su;
        sbroad[1] = su;
    }
    __syncthreads();
    const float su = sbroad[1];

    float acc = 0.0f;
    const float* ap = g_acc + (size_t)b * PPB * II + t;
#pragma unroll 8
    for (int q = 0; q < PPB; q++)
        acc = fmaf(ap[(size_t)q * II], sscale[q], acc);

    read_out[b * II + t] = acc / su;
}

/* ------------------------------------------------------------------ */
/* 4) weights = exp(beta*sim - bmax)/bsum, float4-vectorized.          */
/*    grid = B*M/4/256 = 256, block = 256.                             */
/* ------------------------------------------------------------------ */
__global__ void weights_kernel(const float* __restrict__ beta,
                               const float* __restrict__ sim,
                               float* __restrict__ wout)
{
    const int idx = blockIdx.x * blockDim.x + threadIdx.x;   /* f4 index */
    const int b   = idx >> 11;                               /* MM/4 = 2048 */
    const float bet = beta[b];
    const float mb  = g_bmax[b];
    const float inv = 1.0f / g_bsum[b];

    const float4 s = ((const float4*)sim)[idx];
    float4 w;
    w.x = __expf(fmaf(bet, s.x, -mb)) * inv;
    w.y = __expf(fmaf(bet, s.y, -mb)) * inv;
    w.z = __expf(fmaf(bet, s.z, -mb)) * inv;
    w.w = __expf(fmaf(bet, s.w, -mb)) * inv;
    ((float4*)wout)[idx] = w;
}

/* ------------------------------------------------------------------ */
extern "C" void kernel_launch(void* const* d_in, const int* in_sizes, int n_in,
                              void* d_out, int out_size)
{
    const float* memory = (const float*)d_in[0];   /* [B, M, I] */
    const float* key    = (const float*)d_in[1];   /* [B, I]    */
    const float* beta   = (const float*)d_in[2];   /* [B]       */
    const float* W      = (const float*)d_in[3];   /* [I, I]    */
    const float* bias   = (const float*)d_in[4];   /* [I]       */

    float* out      = (float*)d_out;
    float* w_out    = out;                         /* weights     [B, M] */
    float* read_out = out + (size_t)BB * MM;       /* read_vector [B, I] */
    float* sim_out  = read_out + (size_t)BB * II;  /* similarity  [B, M] */

    proj_kernel   <<<BB, II>>>(key, W, bias);
    main_kernel   <<<BB * BLOCKS_PER_B, 256>>>(memory, beta, sim_out);
    combine_kernel<<<BB, II>>>(read_out);
    weights_kernel<<<(BB * MM) / 4 / 256, 256>>>(beta, sim_out, w_out);
}